// round 15
// baseline (speedup 1.0000x reference)
#include <cuda_runtime.h>
#include <cstdint>
#include <math.h>

// Problem constants
#define CC      512
#define BB      16
#define TT      60
#define NP      196
#define NHEADS  4
#define HD      128
#define CLIPL   6
#define NFRAMES 36
#define TOPK    6
#define TOPM    12

// Output layout (flat float32)
#define OFF1 294912
#define OFF2 3833856

// Block-role layout: producers FIRST
#define NB_Q    64
#define NB_R    64
#define NB_S    8
#define NB_AUD  36
#define NB_BC   288                    // 2 bf rows per block
#define B_Q     0
#define B_R     (B_Q + NB_Q)           // 64
#define B_S     (B_R + NB_R)           // 128
#define B_A     (B_S + NB_S)           // 136
#define B_B     (B_A + NB_AUD)         // 172
#define NB_TOT  (B_B + NB_BC)          // 460

#define NFLAGS  32
#define FSTRIDE 32

__device__ float g_q[CC];
__device__ float g_r[NHEADS * CC];
__device__ float g_sc[NHEADS * NP];
__device__ int   g_pid;
__device__ int   c_qh[NHEADS], c_qhd[NHEADS];
__device__ int   c_r, c_rd;
__device__ int   c_s;
__device__ int   g_pflags[NFLAGS * FSTRIDE];
__device__ int   c_pds[NFLAGS * FSTRIDE];

__device__ __forceinline__ void spin_wait(volatile int* p, int target, int ns) {
    if (threadIdx.x == 0) { while (*p < target) __nanosleep(ns); }
    __syncthreads();
    __threadfence();
}
__device__ __forceinline__ void signal(int* c) {
    __syncthreads();
    __threadfence();
    if (threadIdx.x == 0) atomicAdd(c, 1);
}
__device__ __forceinline__ void consume_reset(int* cd, int n, int* cp) {
    if (threadIdx.x == 0)
        if (atomicAdd(cd, 1) == n - 1) { *cp = 0; *cd = 0; }
}

// ===========================================================================
__global__ void __launch_bounds__(256)
fused(const float* __restrict__ audio,
      const float* __restrict__ patch,
      const float* __restrict__ qst,
      const int*   __restrict__ topk,
      const float* __restrict__ in_w,
      const float* __restrict__ in_b,
      float*       __restrict__ out) {
    __shared__ float S[1100];
    __shared__ int   s_pid, s_last;

    const int bid  = blockIdx.x;
    const int t    = threadIdx.x;
    const int warp = t >> 5, lane = t & 31;

    // ========================= Q blocks (0..63) =============================
    if (bid < B_R) {
        const int row = bid * 8 + warp;
        const float4* x4 = (const float4*)qst;
        const float4* w4 = (const float4*)(in_w + (size_t)row * CC);
        float acc = 0.f;
        #pragma unroll
        for (int i = 0; i < 4; i++) {
            float4 a = w4[lane + 32 * i];
            float4 x = x4[lane + 32 * i];
            acc += a.x * x.x + a.y * x.y + a.z * x.z + a.w * x.w;
        }
        #pragma unroll
        for (int o = 16; o; o >>= 1) acc += __shfl_down_sync(0xffffffffu, acc, o);
        if (lane == 0) g_q[row] = acc + in_b[row];
        signal(&c_qh[bid >> 4]);
        return;
    }

    // ========================= R blocks (64..127) ===========================
    if (bid < B_S) {
        const int rid = bid - B_R;
        const int h   = rid >> 4;
        const int cb  = (rid & 15) * 32;

        const float* Wk = in_w + (size_t)(CC + h * HD + warp * 16) * CC + cb + lane;
        float wk[16];
        #pragma unroll
        for (int j = 0; j < 16; j++) wk[j] = Wk[(size_t)j * CC];

        spin_wait(&c_qh[h], 16, 32);
        consume_reset(&c_qhd[h], 16, &c_qh[h]);

        float acc = 0.f;
        #pragma unroll
        for (int j = 0; j < 16; j++)
            acc += wk[j] * g_q[h * HD + warp * 16 + j];
        S[warp * 32 + lane] = acc;
        __syncthreads();
        if (t < 32) {
            float s = 0.f;
            #pragma unroll
            for (int w = 0; w < 8; w++) s += S[w * 32 + t];
            g_r[h * CC + cb + t] = s;
        }
        signal(&c_r);
        return;
    }

    // ==================== SCORE blocks (128..135; last does pid) ============
    if (bid < B_A) {
        const int gw = (bid - B_S) * 8 + warp;
        const int f0 = topk[0] * CLIPL;
        const float4* p4 = (const float4*)(patch + (size_t)f0 * NP * CC);

        float4 xv0[4];
        #pragma unroll
        for (int i = 0; i < 4; i++) xv0[i] = p4[(size_t)gw * 128 + lane + 32 * i];

        spin_wait(&c_r, NB_R, 32);
        consume_reset(&c_rd, NB_S, &c_r);

        const float4* r4 = (const float4*)g_r;
        for (int pi = 0; pi < 4; pi++) {
            const int n = gw + 64 * pi;
            if (n >= NP) break;
            float4 xv[4];
            if (pi == 0) {
                #pragma unroll
                for (int i = 0; i < 4; i++) xv[i] = xv0[i];
            } else {
                #pragma unroll
                for (int i = 0; i < 4; i++) xv[i] = p4[(size_t)n * 128 + lane + 32 * i];
            }
            float acc[NHEADS] = {0.f, 0.f, 0.f, 0.f};
            #pragma unroll
            for (int h = 0; h < NHEADS; h++)
                #pragma unroll
                for (int i = 0; i < 4; i++) {
                    float4 rv = r4[h * 128 + lane + 32 * i];
                    acc[h] += rv.x * xv[i].x + rv.y * xv[i].y +
                              rv.z * xv[i].z + rv.w * xv[i].w;
                }
            #pragma unroll
            for (int h = 0; h < NHEADS; h++) {
                float v = acc[h];
                #pragma unroll
                for (int o = 16; o; o >>= 1) v += __shfl_down_sync(0xffffffffu, v, o);
                if (lane == 0) g_sc[h * NP + n] = 0.08838834764831845f * v;
            }
        }

        __syncthreads();
        __threadfence();
        if (t == 0) s_last = (atomicAdd(&c_s, 1) == NB_S - 1) ? 1 : 0;
        __syncthreads();
        if (!s_last) return;
        __threadfence();
        if (t == 0) { c_s = 0; s_pid = -1; }

        for (int idx = t; idx < NHEADS * NP; idx += 256) S[idx] = g_sc[idx];
        __syncthreads();

        if (warp < NHEADS) {
            float m = -1e30f;
            for (int nn = lane; nn < NP; nn += 32) m = fmaxf(m, S[warp * NP + nn]);
            #pragma unroll
            for (int o = 16; o; o >>= 1) m = fmaxf(m, __shfl_xor_sync(0xffffffffu, m, o));
            float sum = 0.f;
            for (int nn = lane; nn < NP; nn += 32) sum += expf(S[warp * NP + nn] - m);
            #pragma unroll
            for (int o = 16; o; o >>= 1) sum += __shfl_xor_sync(0xffffffffu, sum, o);
            if (lane == 0) { S[1024 + warp] = m; S[1028 + warp] = 1.f / sum; }
        }
        __syncthreads();

        if (t < NP) {
            float acc = 0.f;
            #pragma unroll
            for (int h = 0; h < NHEADS; h++)
                acc += expf(S[h * NP + t] - S[1024 + h]) * S[1028 + h];
            S[800 + t] = acc * 0.25f;
        }
        __syncthreads();

        if (t < NP) {
            const float wn = S[800 + t];
            int cnt = 0;
            for (int m = 0; m < NP; m++)
                cnt += (S[800 + m] > wn) || (S[800 + m] == wn && m > t);
            if (cnt < TOPM) atomicMax(&s_pid, t);
        }
        __syncthreads();
        if (t == 0) g_pid = s_pid;
        __syncthreads();
        __threadfence();
        if (t < NFLAGS) atomicExch(&g_pflags[t * FSTRIDE], 1);
        return;
    }

    // ========================= AUDIO blocks (136..171) ======================
    if (bid < B_B) {
        const int ab = bid - B_A;
        const float4* a4 = (const float4*)audio;
        float4*       o4 = (float4*)out;
        const int tl = t & 127;
        #pragma unroll
        for (int k = 0; k < 8; k++) {
            const int bf = ab * 16 + k * 2 + (t >> 7);
            const int b = bf / NFRAMES, f = bf % NFRAMES;
            const int seg   = topk[b * TOPK + f / CLIPL];
            const int frame = seg * CLIPL + (f % CLIPL);
            o4[(size_t)bf * 128 + tl] = a4[((size_t)b * TT + frame) * 128 + tl];
        }
        const int tid = ab * 256 + t;
        if (tid < 3136) {
            const int f0 = topk[0] * CLIPL;
            const char* pr = (const char*)(patch + (size_t)f0 * NP * CC);
            asm volatile("prefetch.global.L2 [%0];" :: "l"(pr + (size_t)tid * 128));
        }
        return;
    }

    // ========================= BCAST blocks (172..459) ======================
    {
        const int ab = bid - B_B;                  // 0..287, 2 bf rows each
        const int fg = (ab % NFLAGS) * FSTRIDE;

        spin_wait(&g_pflags[fg], 1, 128);
        const int pid = g_pid;

        const float4* p4 = (const float4*)patch;
        float4*       o4 = (float4*)out;
        const int tl = t & 127, half = t >> 7;     // half selects the bf row

        const int bf = ab * 2 + half;              // 0..575
        const int b = bf / NFRAMES, f = bf % NFRAMES;
        const int seg   = topk[b * TOPK + f / CLIPL];
        const int frame = seg * CLIPL + (f % CLIPL);
        const float4 p = p4[(((size_t)b * TT + frame) * NP + pid) * 128 + tl];
        const size_t base1 = OFF1 / 4 + (size_t)bf * TOPM * 128 + tl;
        const size_t base2 = OFF2 / 4 + (size_t)bf * TOPM * 128 + tl;
        #pragma unroll
        for (int m = 0; m < TOPM; m++) {
            o4[base1 + (size_t)m * 128] = p;
            o4[base2 + (size_t)m * 128] = p;
        }
        consume_reset(&c_pds[fg], NB_BC / NFLAGS, &g_pflags[fg]);
    }
}

// ---------------------------------------------------------------------------
extern "C" void kernel_launch(void* const* d_in, const int* in_sizes, int n_in,
                              void* d_out, int out_size) {
    const float* audio = (const float*)d_in[0];
    const float* patch = (const float*)d_in[1];
    const float* qst   = (const float*)d_in[2];
    const int*   topk  = (const int*)  d_in[3];
    const float* in_w  = (const float*)d_in[4];
    const float* in_b  = (const float*)d_in[5];
    float* out = (float*)d_out;

    fused<<<NB_TOT, 256>>>(audio, patch, qst, topk, in_w, in_b, out);
}

// round 16
// speedup vs baseline: 1.0102x; 1.0102x over previous
#include <cuda_runtime.h>
#include <cstdint>
#include <math.h>

// Problem constants
#define CC      512
#define BB      16
#define TT      60
#define NP      196
#define NHEADS  4
#define HD      128
#define CLIPL   6
#define NFRAMES 36
#define TOPK    6
#define TOPM    12

// Output layout (flat float32)
#define OFF1 294912
#define OFF2 3833856

// Block-role layout: producers FIRST
#define NB_Q    64                     // q: 64 blocks x 8 warps = 512 rows
#define NB_R    64                     // r: 4 heads x 16 col-slices
#define NB_S    8                      // scores (last finisher also does pid)
#define NB_AUD  36                     // audio gather + prefetch
#define NB_BC   576                    // broadcast
#define B_Q     0
#define B_R     (B_Q + NB_Q)           // 64
#define B_S     (B_R + NB_R)           // 128
#define B_A     (B_S + NB_S)           // 136
#define B_B     (B_A + NB_AUD)         // 172
#define NB_TOT  (B_B + NB_BC)          // 748

#define NFLAGS  64                     // distributed pid flags
#define FSTRIDE 32                     // 128B apart (ints)

// Scratch + sync (device globals; all counters return to 0 every launch)
__device__ float g_q[CC];
__device__ float g_r[NHEADS * CC];
__device__ float g_sc[NHEADS * NP];
__device__ int   g_pid;
__device__ int   c_qh[NHEADS], c_qhd[NHEADS];   // per-head q prod(16)/cons(16)
__device__ int   c_r, c_rd;                     // r produced (64) / consumed (8)
__device__ int   c_s;                           // score ticket (8; last does pid)
__device__ int   g_pflags[NFLAGS * FSTRIDE];    // distributed flags
__device__ int   c_pds[NFLAGS * FSTRIDE];       // per-flag consume counters (9 each)

// ---- sync helpers: TIGHT polling, no nanosleep ----------------------------
__device__ __forceinline__ void spin_wait(volatile int* p, int target) {
    if (threadIdx.x == 0) { while (*p < target) { } }
    __syncthreads();
    __threadfence();                  // acquire
}
__device__ __forceinline__ void signal(int* c) {
    __syncthreads();
    __threadfence();                  // release
    if (threadIdx.x == 0) atomicAdd(c, 1);
}
__device__ __forceinline__ void consume_reset(int* cd, int n, int* cp) {
    if (threadIdx.x == 0)
        if (atomicAdd(cd, 1) == n - 1) { *cp = 0; *cd = 0; }
}

// ===========================================================================
__global__ void __launch_bounds__(256)
fused(const float* __restrict__ audio,
      const float* __restrict__ patch,
      const float* __restrict__ qst,
      const int*   __restrict__ topk,
      const float* __restrict__ in_w,
      const float* __restrict__ in_b,
      float*       __restrict__ out) {
    __shared__ float S[1100];                       // role-shared scratch
    __shared__ int   s_pid, s_last;

    const int bid  = blockIdx.x;
    const int t    = threadIdx.x;
    const int warp = t >> 5, lane = t & 31;

    // ========================= Q blocks (0..63) =============================
    if (bid < B_R) {
        const int row = bid * 8 + warp;            // warp per row
        const float4* x4 = (const float4*)qst;     // batch 0
        const float4* w4 = (const float4*)(in_w + (size_t)row * CC);
        float acc = 0.f;
        #pragma unroll
        for (int i = 0; i < 4; i++) {
            float4 a = w4[lane + 32 * i];
            float4 x = x4[lane + 32 * i];
            acc += a.x * x.x + a.y * x.y + a.z * x.z + a.w * x.w;
        }
        #pragma unroll
        for (int o = 16; o; o >>= 1) acc += __shfl_down_sync(0xffffffffu, acc, o);
        if (lane == 0) g_q[row] = acc + in_b[row];
        signal(&c_qh[bid >> 4]);                   // per-head counter
        return;
    }

    // ========================= R blocks (64..127) ===========================
    if (bid < B_S) {
        const int rid = bid - B_R;
        const int h   = rid >> 4;                  // head
        const int cb  = (rid & 15) * 32;           // col base

        // PREWORK: 16 Wk loads (independent of q) before polling
        const float* Wk = in_w + (size_t)(CC + h * HD + warp * 16) * CC + cb + lane;
        float wk[16];
        #pragma unroll
        for (int j = 0; j < 16; j++) wk[j] = Wk[(size_t)j * CC];

        spin_wait(&c_qh[h], 16);
        consume_reset(&c_qhd[h], 16, &c_qh[h]);

        float acc = 0.f;
        #pragma unroll
        for (int j = 0; j < 16; j++)
            acc += wk[j] * g_q[h * HD + warp * 16 + j];
        S[warp * 32 + lane] = acc;
        __syncthreads();
        if (t < 32) {
            float s = 0.f;
            #pragma unroll
            for (int w = 0; w < 8; w++) s += S[w * 32 + t];
            g_r[h * CC + cb + t] = s;
        }
        signal(&c_r);
        return;
    }

    // ==================== SCORE blocks (128..135; last does pid) ============
    if (bid < B_A) {
        const int gw = (bid - B_S) * 8 + warp;     // global warp 0..63
        const int f0 = topk[0] * CLIPL;
        const float4* p4 = (const float4*)(patch + (size_t)f0 * NP * CC);

        // PREWORK: first patch row before polling
        float4 xv0[4];
        #pragma unroll
        for (int i = 0; i < 4; i++) xv0[i] = p4[(size_t)gw * 128 + lane + 32 * i];

        spin_wait(&c_r, NB_R);
        consume_reset(&c_rd, NB_S, &c_r);

        const float4* r4 = (const float4*)g_r;
        for (int pi = 0; pi < 4; pi++) {
            const int n = gw + 64 * pi;
            if (n >= NP) break;
            float4 xv[4];
            if (pi == 0) {
                #pragma unroll
                for (int i = 0; i < 4; i++) xv[i] = xv0[i];
            } else {
                #pragma unroll
                for (int i = 0; i < 4; i++) xv[i] = p4[(size_t)n * 128 + lane + 32 * i];
            }
            float acc[NHEADS] = {0.f, 0.f, 0.f, 0.f};
            #pragma unroll
            for (int h = 0; h < NHEADS; h++)
                #pragma unroll
                for (int i = 0; i < 4; i++) {
                    float4 rv = r4[h * 128 + lane + 32 * i];
                    acc[h] += rv.x * xv[i].x + rv.y * xv[i].y +
                              rv.z * xv[i].z + rv.w * xv[i].w;
                }
            #pragma unroll
            for (int h = 0; h < NHEADS; h++) {
                float v = acc[h];
                #pragma unroll
                for (int o = 16; o; o >>= 1) v += __shfl_down_sync(0xffffffffu, v, o);
                if (lane == 0) g_sc[h * NP + n] = 0.08838834764831845f * v;
            }
        }

        // ticket: last-finishing score block performs pid selection
        __syncthreads();
        __threadfence();                            // release own scores
        if (t == 0) s_last = (atomicAdd(&c_s, 1) == NB_S - 1) ? 1 : 0;
        __syncthreads();
        if (!s_last) return;
        __threadfence();                            // acquire others' scores
        if (t == 0) { c_s = 0; s_pid = -1; }

        for (int idx = t; idx < NHEADS * NP; idx += 256) S[idx] = g_sc[idx];
        __syncthreads();

        // per-head softmax stats (warps 0-3)
        if (warp < NHEADS) {
            float m = -1e30f;
            for (int nn = lane; nn < NP; nn += 32) m = fmaxf(m, S[warp * NP + nn]);
            #pragma unroll
            for (int o = 16; o; o >>= 1) m = fmaxf(m, __shfl_xor_sync(0xffffffffu, m, o));
            float sum = 0.f;
            for (int nn = lane; nn < NP; nn += 32) sum += expf(S[warp * NP + nn] - m);
            #pragma unroll
            for (int o = 16; o; o >>= 1) sum += __shfl_xor_sync(0xffffffffu, sum, o);
            if (lane == 0) { S[1024 + warp] = m; S[1028 + warp] = 1.f / sum; }
        }
        __syncthreads();

        // mean-over-heads weights
        if (t < NP) {
            float acc = 0.f;
            #pragma unroll
            for (int h = 0; h < NHEADS; h++)
                acc += expf(S[h * NP + t] - S[1024 + h]) * S[1028 + h];
            S[800 + t] = acc * 0.25f;
        }
        __syncthreads();

        // pid = max index among top-12 (stable-argsort tie-break)
        if (t < NP) {
            const float wn = S[800 + t];
            int cnt = 0;
            for (int m = 0; m < NP; m++)
                cnt += (S[800 + m] > wn) || (S[800 + m] == wn && m > t);
            if (cnt < TOPM) atomicMax(&s_pid, t);
        }
        __syncthreads();
        if (t == 0) g_pid = s_pid;
        __syncthreads();
        __threadfence();                            // release pid
        // fan-out: 64 distributed flags, one store each by 64 threads
        if (t < NFLAGS) atomicExch(&g_pflags[t * FSTRIDE], 1);
        return;
    }

    // ========================= AUDIO blocks (136..171) ======================
    if (bid < B_B) {
        const int ab = bid - B_A;
        const float4* a4 = (const float4*)audio;
        float4*       o4 = (float4*)out;
        const int tl = t & 127;
        #pragma unroll
        for (int k = 0; k < 8; k++) {
            const int bf = ab * 16 + k * 2 + (t >> 7);
            const int b = bf / NFRAMES, f = bf % NFRAMES;
            const int seg   = topk[b * TOPK + f / CLIPL];
            const int frame = seg * CLIPL + (f % CLIPL);
            o4[(size_t)bf * 128 + tl] = a4[((size_t)b * TT + frame) * 128 + tl];
        }
        // prefetch score-phase patch rows (400KB) into L2
        const int tid = ab * 256 + t;
        if (tid < 3136) {
            const int f0 = topk[0] * CLIPL;
            const char* pr = (const char*)(patch + (size_t)f0 * NP * CC);
            asm volatile("prefetch.global.L2 [%0];" :: "l"(pr + (size_t)tid * 128));
        }
        return;
    }

    // ========================= BCAST blocks (172..747) ======================
    {
        const int bf = bid - B_B;                  // 0..575
        const int b = bf / NFRAMES, f = bf % NFRAMES;
        const int seg   = topk[b * TOPK + f / CLIPL];
        const int frame = seg * CLIPL + (f % CLIPL);
        const int fg = (bf % NFLAGS) * FSTRIDE;    // this block's flag

        spin_wait(&g_pflags[fg], 1);
        const int pid = g_pid;

        const float4* p4 = (const float4*)patch;
        float4*       o4 = (float4*)out;
        const int tl = t & 127, reg = t >> 7;      // halves handle the 2 regions
        const float4 p = p4[(((size_t)b * TT + frame) * NP + pid) * 128 + tl];
        const size_t base = (reg ? OFF2 : OFF1) / 4 + (size_t)bf * TOPM * 128 + tl;
        #pragma unroll
        for (int m = 0; m < TOPM; m++)
            o4[base + (size_t)m * 128] = p;

        consume_reset(&c_pds[fg], NB_BC / NFLAGS, &g_pflags[fg]);
    }
}

// ---------------------------------------------------------------------------
extern "C" void kernel_launch(void* const* d_in, const int* in_sizes, int n_in,
                              void* d_out, int out_size) {
    const float* audio = (const float*)d_in[0];   // (16,60,512)
    const float* patch = (const float*)d_in[1];   // (16,60,196,512)
    const float* qst   = (const float*)d_in[2];   // (16,512)
    const int*   topk  = (const int*)  d_in[3];   // (16,1,6)
    const float* in_w  = (const float*)d_in[4];   // (1536,512)
    const float* in_b  = (const float*)d_in[5];   // (1536,)
    float* out = (float*)d_out;

    fused<<<NB_TOT, 256>>>(audio, patch, qst, topk, in_w, in_b, out);
}